// round 4
// baseline (speedup 1.0000x reference)
#include <cuda_runtime.h>

// Dense backward image warp, bilinear, fp32.
// image: [B, H, W, 3], flow: [B, H, W, 2] (y, x), out: [B, H, W, 3]
// query = (y, x) - flow; floor clamped to [0, size-2]; alpha clamped to [0,1].

#define Bn 16
#define Hn 720
#define Wn 1280

__global__ __launch_bounds__(256) void backwarp_kernel(
    const float* __restrict__ img,
    const float* __restrict__ flow,
    float* __restrict__ out)
{
    const int HW = Hn * Wn;
    const int total = Bn * HW;

    int t  = blockIdx.x * blockDim.x + threadIdx.x;
    int p0 = t * 4;                      // first of 4 consecutive pixels
    if (p0 >= total) return;

    // W % 4 == 0 and p0 % 4 == 0 -> all 4 pixels share batch and row.
    int b   = p0 / HW;
    int rem = p0 - b * HW;
    int y   = rem / Wn;
    int x0  = rem - y * Wn;

    // flow: 2 floats/pixel -> 8 floats = 2x float4 (32B aligned: p0*2 % 8 == 0)
    const float4 f01 = *reinterpret_cast<const float4*>(flow + (size_t)p0 * 2);
    const float4 f23 = *reinterpret_cast<const float4*>(flow + (size_t)p0 * 2 + 4);

    const float fyv[4] = { f01.x, f01.z, f23.x, f23.z };
    const float fxv[4] = { f01.y, f01.w, f23.y, f23.w };

    const float* __restrict__ imgb = img + (size_t)b * HW * 3;

    float res[4][3];

    #pragma unroll
    for (int i = 0; i < 4; i++) {
        float qy = (float)y        - fyv[i];
        float qx = (float)(x0 + i) - fxv[i];

        float flY = fminf(fmaxf(floorf(qy), 0.0f), (float)(Hn - 2));
        float flX = fminf(fmaxf(floorf(qx), 0.0f), (float)(Wn - 2));
        float ay  = fminf(fmaxf(qy - flY, 0.0f), 1.0f);
        float ax  = fminf(fmaxf(qx - flX, 0.0f), 1.0f);

        int iy = (int)flY;
        int ix = (int)flX;

        const float* __restrict__ pt = imgb + ((size_t)iy * Wn + ix) * 3;
        const float* __restrict__ pb = pt + Wn * 3;

        // 4 taps x 3 channels
        float tl0 = pt[0], tl1 = pt[1], tl2 = pt[2];
        float tr0 = pt[3], tr1 = pt[4], tr2 = pt[5];
        float bl0 = pb[0], bl1 = pb[1], bl2 = pb[2];
        float br0 = pb[3], br1 = pb[4], br2 = pb[5];

        // interp_top = tl + ax*(tr - tl); interp_bot = bl + ax*(br - bl)
        float top0 = fmaf(ax, tr0 - tl0, tl0);
        float top1 = fmaf(ax, tr1 - tl1, tl1);
        float top2 = fmaf(ax, tr2 - tl2, tl2);
        float bot0 = fmaf(ax, br0 - bl0, bl0);
        float bot1 = fmaf(ax, br1 - bl1, bl1);
        float bot2 = fmaf(ax, br2 - bl2, bl2);

        res[i][0] = fmaf(ay, bot0 - top0, top0);
        res[i][1] = fmaf(ay, bot1 - top1, top1);
        res[i][2] = fmaf(ay, bot2 - top2, top2);
    }

    // 12 contiguous floats -> 3x float4 (48B aligned: p0*3 % 4 == 0, p0 % 4 == 0)
    float* __restrict__ op = out + (size_t)p0 * 3;
    float4 o0 = make_float4(res[0][0], res[0][1], res[0][2], res[1][0]);
    float4 o1 = make_float4(res[1][1], res[1][2], res[2][0], res[2][1]);
    float4 o2 = make_float4(res[2][2], res[3][0], res[3][1], res[3][2]);
    reinterpret_cast<float4*>(op)[0] = o0;
    reinterpret_cast<float4*>(op)[1] = o1;
    reinterpret_cast<float4*>(op)[2] = o2;
}

extern "C" void kernel_launch(void* const* d_in, const int* in_sizes, int n_in,
                              void* d_out, int out_size)
{
    const float* image = (const float*)d_in[0];  // [B,H,W,3]
    const float* flow  = (const float*)d_in[1];  // [B,H,W,2]
    float* out         = (float*)d_out;          // [B,H,W,3]

    const int total   = Bn * Hn * Wn;            // 14,745,600 pixels
    const int threads = 256;
    const int blocks  = (total / 4 + threads - 1) / threads;  // 14400 exactly

    backwarp_kernel<<<blocks, threads>>>(image, flow, out);
}

// round 5
// speedup vs baseline: 1.3425x; 1.3425x over previous
#include <cuda_runtime.h>

// Dense backward image warp, bilinear, fp32.
// image: [B, H, W, 3], flow: [B, H, W, 2] (y, x), out: [B, H, W, 3]
// query = (y, x) - flow; floor clamped to [0, size-2]; alpha clamped to [0,1].
//
// 1 pixel per thread: minimizes lane stride on gather taps (12 B) so each
// L1 request touches ~3-4 lines instead of ~12. Output repacked via smem
// into coalesced float4 stores.

#define Bn 16
#define Hn 720
#define Wn 1280

__global__ __launch_bounds__(256) void backwarp_kernel(
    const float* __restrict__ img,
    const float* __restrict__ flow,
    float* __restrict__ out)
{
    const int HW = Hn * Wn;

    __shared__ float s_out[256 * 3];   // 3 KB repack buffer

    const int tid = threadIdx.x;
    const int p   = blockIdx.x * 256 + tid;   // pixel index (grid is exact)

    // decompose pixel index
    int b   = p / HW;
    int rem = p - b * HW;
    int y   = rem / Wn;
    int x   = rem - y * Wn;

    // flow: float2 per pixel, 8-B aligned, streaming (no reuse)
    const float2 f = __ldcs(reinterpret_cast<const float2*>(flow) + p);

    float qy = (float)y - f.x;
    float qx = (float)x - f.y;

    float flY = fminf(fmaxf(floorf(qy), 0.0f), (float)(Hn - 2));
    float flX = fminf(fmaxf(floorf(qx), 0.0f), (float)(Wn - 2));
    float ay  = fminf(fmaxf(qy - flY, 0.0f), 1.0f);
    float ax  = fminf(fmaxf(qx - flX, 0.0f), 1.0f);

    int iy = (int)flY;
    int ix = (int)flX;

    const float* __restrict__ pt = img + ((size_t)b * HW + (size_t)iy * Wn + ix) * 3;
    const float* __restrict__ pb = pt + Wn * 3;

    // 4 taps x 3 channels (scalar: base only 4-B aligned)
    float tl0 = pt[0], tl1 = pt[1], tl2 = pt[2];
    float tr0 = pt[3], tr1 = pt[4], tr2 = pt[5];
    float bl0 = pb[0], bl1 = pb[1], bl2 = pb[2];
    float br0 = pb[3], br1 = pb[4], br2 = pb[5];

    // interp_top = tl + ax*(tr - tl); interp_bot = bl + ax*(br - bl)
    float top0 = fmaf(ax, tr0 - tl0, tl0);
    float top1 = fmaf(ax, tr1 - tl1, tl1);
    float top2 = fmaf(ax, tr2 - tl2, tl2);
    float bot0 = fmaf(ax, br0 - bl0, bl0);
    float bot1 = fmaf(ax, br1 - bl1, bl1);
    float bot2 = fmaf(ax, br2 - bl2, bl2);

    // bank-conflict-free STS (stride 3, gcd(3,32)=1)
    s_out[tid * 3 + 0] = fmaf(ay, bot0 - top0, top0);
    s_out[tid * 3 + 1] = fmaf(ay, bot1 - top1, top1);
    s_out[tid * 3 + 2] = fmaf(ay, bot2 - top2, top2);

    __syncthreads();

    // 256 px * 3 ch = 768 floats = 192 float4, fully coalesced, streaming.
    // Block store base = blockIdx.x * 3072 B -> 16-B aligned.
    if (tid < 192) {
        float4 v = reinterpret_cast<const float4*>(s_out)[tid];
        __stcs(reinterpret_cast<float4*>(out) + (size_t)blockIdx.x * 192 + tid, v);
    }
}

extern "C" void kernel_launch(void* const* d_in, const int* in_sizes, int n_in,
                              void* d_out, int out_size)
{
    const float* image = (const float*)d_in[0];  // [B,H,W,3]
    const float* flow  = (const float*)d_in[1];  // [B,H,W,2]
    float* out         = (float*)d_out;          // [B,H,W,3]

    const int total   = Bn * Hn * Wn;            // 14,745,600 pixels
    const int threads = 256;
    const int blocks  = total / threads;         // 57,600 exactly

    backwarp_kernel<<<blocks, threads>>>(image, flow, out);
}